// round 4
// baseline (speedup 1.0000x reference)
#include <cuda_runtime.h>

#define H 5
#define HID 160
#define NG 8
#define NC 20
#define MAXN 50000
#define MAXE 800000
#define MAXET (MAXN + MAXE)

// ---------------- device scratch (static; no runtime allocation) ----------------
__device__ float    g_feat[MAXN * HID];     // h = x @ W (pre-aggregation features)
__device__ float    g_hidden[MAXN * HID];   // layer outputs
__device__ float    g_als[MAXN * H];
__device__ float    g_ald[MAXN * H];
__device__ unsigned g_maxu[MAXN * H];
__device__ float    g_sum[MAXN * H];
__device__ int      g_rowptr[MAXN + 1];
__device__ int      g_cursor[MAXN];
__device__ int      g_cnt[MAXN];
__device__ int      g_eids[MAXET];
__device__ float    g_pool[NG * HID];
__device__ int      g_gcnt[NG];
__device__ int      g_idx64;

// ---------------- helpers ----------------
__device__ __forceinline__ long long ldidx(const void* p, long long i) {
    return g_idx64 ? ((const long long*)p)[i] : (long long)((const int*)p)[i];
}
__device__ __forceinline__ unsigned fkey(float f) {
    unsigned u = __float_as_uint(f);
    return (u & 0x80000000u) ? ~u : (u | 0x80000000u);
}
__device__ __forceinline__ float fdec(unsigned k) {
    return (k & 0x80000000u) ? __uint_as_float(k & 0x7fffffffu)
                             : __uint_as_float(~k);
}

// ---------------- index dtype detection ----------------
__global__ void detect_kernel(const void* ei) {
    if (blockIdx.x == 0 && threadIdx.x == 0) {
        const int* p = (const int*)ei;
        int is64 = 1;
        for (int i = 0; i < 512; ++i)
            if (p[2 * i + 1] != 0) { is64 = 0; break; }
        g_idx64 = is64;
    }
}

// ---------------- CSR build (dst-sorted edge list) ----------------
__global__ void zero_csr_kernel(int n) {
    int i = blockIdx.x * blockDim.x + threadIdx.x;
    if (i < n) g_cnt[i] = 0;
}

__global__ void count_kernel(const void* ei, int E, int N) {
    int e = blockIdx.x * blockDim.x + threadIdx.x;
    if (e >= E + N) return;
    int d = (e < E) ? (int)ldidx(ei, (long long)E + e) : (e - E);
    atomicAdd(&g_cnt[d], 1);
}

__global__ void scan_kernel(int n) {
    __shared__ int s[1024];
    __shared__ int carry;
    int tid = threadIdx.x;
    if (tid == 0) carry = 0;
    __syncthreads();
    for (int base = 0; base < n; base += 1024) {
        int i = base + tid;
        int v = (i < n) ? g_cnt[i] : 0;
        s[tid] = v;
        __syncthreads();
        for (int off = 1; off < 1024; off <<= 1) {
            int t = (tid >= off) ? s[tid - off] : 0;
            __syncthreads();
            s[tid] += t;
            __syncthreads();
        }
        if (i < n) g_rowptr[i] = carry + s[tid] - v;
        __syncthreads();
        if (tid == 0) carry += s[1023];
        __syncthreads();
    }
    if (tid == 0) g_rowptr[n] = carry;
}

__global__ void copy_cursor_kernel(int n) {
    int i = blockIdx.x * blockDim.x + threadIdx.x;
    if (i < n) g_cursor[i] = g_rowptr[i];
}

__global__ void fill_kernel(const void* ei, int E, int N) {
    int e = blockIdx.x * blockDim.x + threadIdx.x;
    if (e >= E + N) return;
    int d = (e < E) ? (int)ldidx(ei, (long long)E + e) : (e - E);
    int pos = atomicAdd(&g_cursor[d], 1);
    g_eids[pos] = e;
}

// ---------------- GEMM: C[M,160] = A[M,K] @ W[K,160] (+optional bias+leaky) --------
// BM=64, BN=160(full), BK=16, 256 threads, each thread 8x5 outputs.
__global__ __launch_bounds__(256) void gemm_kernel(
    const float* __restrict__ A, const float* __restrict__ W, float* __restrict__ C,
    int M, int K, const float* __restrict__ bias, int act)
{
    __shared__ float sA[64][16];
    __shared__ float sW[16][160];
    int tid = threadIdx.x;
    int ty  = tid >> 5;   // 0..7
    int tx  = tid & 31;   // 0..31
    int r0  = blockIdx.x * 64;

    float acc[8][5];
#pragma unroll
    for (int i = 0; i < 8; i++)
#pragma unroll
        for (int j = 0; j < 5; j++) acc[i][j] = 0.f;

    for (int k0 = 0; k0 < K; k0 += 16) {
#pragma unroll
        for (int u = 0; u < 4; u++) {
            int i = tid * 4 + u;
            int m = i >> 4, k = i & 15;
            int gr = r0 + m, gk = k0 + k;
            sA[m][k] = (gr < M && gk < K) ? A[(long long)gr * K + gk] : 0.f;
        }
#pragma unroll
        for (int u = 0; u < 10; u++) {
            int i = tid + u * 256;
            int k = i / 160, n = i % 160;
            int gk = k0 + k;
            sW[k][n] = (gk < K) ? W[gk * 160 + n] : 0.f;
        }
        __syncthreads();
#pragma unroll
        for (int k = 0; k < 16; k++) {
            float wv[5];
#pragma unroll
            for (int j = 0; j < 5; j++) wv[j] = sW[k][tx + 32 * j];
#pragma unroll
            for (int i = 0; i < 8; i++) {
                float av = sA[ty * 8 + i][k];
#pragma unroll
                for (int j = 0; j < 5; j++) acc[i][j] += av * wv[j];
            }
        }
        __syncthreads();
    }
#pragma unroll
    for (int i = 0; i < 8; i++) {
        int gr = r0 + ty * 8 + i;
        if (gr < M) {
#pragma unroll
            for (int j = 0; j < 5; j++) {
                int c = tx + 32 * j;
                float v = acc[i][j];
                if (act) { v += bias[c]; v = v > 0.f ? v : 0.01f * v; }
                C[(long long)gr * 160 + c] = v;
            }
        }
    }
}

// ---------------- attention coefficients: al_s/al_d [N,H] ----------------
__global__ void attcoef_kernel(const float* __restrict__ feat,
                               const float* __restrict__ asrc,
                               const float* __restrict__ adst, int N)
{
    int warp = (blockIdx.x * blockDim.x + threadIdx.x) >> 5;
    int lane = threadIdx.x & 31;
    if (warp >= N) return;
#pragma unroll
    for (int h = 0; h < H; h++) {
        float v  = feat[(long long)warp * HID + h * 32 + lane];
        float ps = v * asrc[h * 32 + lane];
        float pd = v * adst[h * 32 + lane];
#pragma unroll
        for (int off = 16; off; off >>= 1) {
            ps += __shfl_down_sync(0xffffffffu, ps, off);
            pd += __shfl_down_sync(0xffffffffu, pd, off);
        }
        if (lane == 0) {
            g_als[warp * H + h] = ps;
            g_ald[warp * H + h] = pd;
        }
    }
}

__global__ void zero_sm_kernel(int n) {
    int i = blockIdx.x * blockDim.x + threadIdx.x;
    if (i < n) { g_maxu[i] = 0u; g_sum[i] = 0.f; }
}

// ---------------- edge softmax pass 1: segment max ----------------
__global__ void edge_max_kernel(const void* ei, int E, int N) {
    int e = blockIdx.x * blockDim.x + threadIdx.x;
    if (e >= E + N) return;
    int s, d;
    if (e < E) { s = (int)ldidx(ei, e); d = (int)ldidx(ei, (long long)E + e); }
    else       { s = d = e - E; }
#pragma unroll
    for (int h = 0; h < H; h++) {
        float l = g_als[s * H + h] + g_ald[d * H + h];
        l = l > 0.f ? l : 0.2f * l;
        atomicMax(&g_maxu[d * H + h], fkey(l));
    }
}

// ---------------- edge softmax pass 2: exp + segment sum ----------------
__global__ void edge_exp_kernel(const void* ei, float* __restrict__ alpha, int E, int N) {
    int e = blockIdx.x * blockDim.x + threadIdx.x;
    if (e >= E + N) return;
    int s, d;
    if (e < E) { s = (int)ldidx(ei, e); d = (int)ldidx(ei, (long long)E + e); }
    else       { s = d = e - E; }
#pragma unroll
    for (int h = 0; h < H; h++) {
        float l = g_als[s * H + h] + g_ald[d * H + h];
        l = l > 0.f ? l : 0.2f * l;
        float m  = fdec(g_maxu[d * H + h]);
        float ex = expf(l - m);
        alpha[(long long)e * H + h] = ex;
        atomicAdd(&g_sum[d * H + h], ex);
    }
}

// ---------------- aggregation + alpha normalize + bias + leaky + LayerNorm -------
// One warp per destination node; 5 accumulator regs/lane hold the full 160-ch row.
__global__ __launch_bounds__(256) void aggregate_kernel(
    const void* ei, int E,
    float* __restrict__ alpha,            // in: exp values; out: normalized
    const float* __restrict__ bias,
    const float* __restrict__ lns, const float* __restrict__ lnb,
    int N)
{
    int warp = (blockIdx.x * blockDim.x + threadIdx.x) >> 5;
    int lane = threadIdx.x & 31;
    if (warp >= N) return;
    int n = warp;

    float sinv = 0.f;
    if (lane < H) sinv = 1.f / (g_sum[n * H + lane] + 1e-16f);

    float acc0 = 0.f, acc1 = 0.f, acc2 = 0.f, acc3 = 0.f, acc4 = 0.f;
    int p0 = g_rowptr[n], p1 = g_rowptr[n + 1];
    for (int p = p0; p < p1; ++p) {
        int e = g_eids[p];
        int s = (e < E) ? (int)ldidx(ei, e) : (e - E);
        float an = 0.f;
        if (lane < H) {
            an = alpha[(long long)e * H + lane] * sinv;
            alpha[(long long)e * H + lane] = an;
        }
        float a0 = __shfl_sync(0xffffffffu, an, 0);
        float a1 = __shfl_sync(0xffffffffu, an, 1);
        float a2 = __shfl_sync(0xffffffffu, an, 2);
        float a3 = __shfl_sync(0xffffffffu, an, 3);
        float a4 = __shfl_sync(0xffffffffu, an, 4);
        const float* f = g_feat + (long long)s * HID;
        acc0 += f[lane]       * a0;
        acc1 += f[32 + lane]  * a1;
        acc2 += f[64 + lane]  * a2;
        acc3 += f[96 + lane]  * a3;
        acc4 += f[128 + lane] * a4;
    }
    // bias + leaky(0.01)
    float v0 = acc0 + bias[lane];        v0 = v0 > 0.f ? v0 : 0.01f * v0;
    float v1 = acc1 + bias[32 + lane];   v1 = v1 > 0.f ? v1 : 0.01f * v1;
    float v2 = acc2 + bias[64 + lane];   v2 = v2 > 0.f ? v2 : 0.01f * v2;
    float v3 = acc3 + bias[96 + lane];   v3 = v3 > 0.f ? v3 : 0.01f * v3;
    float v4 = acc4 + bias[128 + lane];  v4 = v4 > 0.f ? v4 : 0.01f * v4;
    // LayerNorm over 160
    float sum = v0 + v1 + v2 + v3 + v4;
#pragma unroll
    for (int off = 16; off; off >>= 1) sum += __shfl_xor_sync(0xffffffffu, sum, off);
    float mu = sum * (1.f / 160.f);
    float d0 = v0 - mu, d1 = v1 - mu, d2 = v2 - mu, d3 = v3 - mu, d4 = v4 - mu;
    float sq = d0 * d0 + d1 * d1 + d2 * d2 + d3 * d3 + d4 * d4;
#pragma unroll
    for (int off = 16; off; off >>= 1) sq += __shfl_xor_sync(0xffffffffu, sq, off);
    float rstd = rsqrtf(sq * (1.f / 160.f) + 1e-5f);
    float* o = g_hidden + (long long)n * HID;
    o[lane]       = d0 * rstd * lns[lane]       + lnb[lane];
    o[32 + lane]  = d1 * rstd * lns[32 + lane]  + lnb[32 + lane];
    o[64 + lane]  = d2 * rstd * lns[64 + lane]  + lnb[64 + lane];
    o[96 + lane]  = d3 * rstd * lns[96 + lane]  + lnb[96 + lane];
    o[128 + lane] = d4 * rstd * lns[128 + lane] + lnb[128 + lane];
}

// ---------------- pooling ----------------
__global__ void zero_pool_kernel() {
    int i = blockIdx.x * blockDim.x + threadIdx.x;
    if (i < NG * HID) g_pool[i] = 0.f;
    if (i < NG) g_gcnt[i] = 0;
}

__global__ void pool_kernel(const float* __restrict__ xo, const void* batchp, int N) {
    int c  = threadIdx.x;                 // 160 threads
    int n0 = blockIdx.x * 128;
    int n1 = n0 + 128; if (n1 > N) n1 = N;
    float acc = 0.f; int cur = -1; int cnt = 0;
    for (int n = n0; n < n1; ++n) {
        int g = (int)ldidx(batchp, n);
        if (g != cur) {
            if (cur >= 0) {
                atomicAdd(&g_pool[cur * HID + c], acc);
                if (c == 0) atomicAdd(&g_gcnt[cur], cnt);
            }
            acc = 0.f; cnt = 0; cur = g;
        }
        acc += xo[(long long)n * HID + c];
        cnt++;
    }
    if (cur >= 0) {
        atomicAdd(&g_pool[cur * HID + c], acc);
        if (c == 0) atomicAdd(&g_gcnt[cur], cnt);
    }
}

// ---------------- tiny MLP head ----------------
__global__ void mlp_kernel(const float* __restrict__ W1, const float* __restrict__ b1,
                           const float* __restrict__ lns, const float* __restrict__ lnb,
                           const float* __restrict__ W2, const float* __restrict__ b2,
                           float* __restrict__ rec)
{
    __shared__ float sp[NG][HID];
    __shared__ float sz[HID];
    __shared__ float red[HID];
    __shared__ float smu, srstd;
    int c = threadIdx.x;                  // 160 threads
    for (int g = 0; g < NG; g++) {
        float cf = (float)g_gcnt[g];
        if (cf < 1.f) cf = 1.f;
        sp[g][c] = g_pool[g * HID + c] / cf;
    }
    __syncthreads();
    for (int g = 0; g < NG; g++) {
        float z = b1[c];
        for (int k = 0; k < HID; k++) z += sp[g][k] * W1[k * HID + c];
        red[c] = z;
        __syncthreads();
        if (c == 0) { float s = 0.f; for (int k = 0; k < HID; k++) s += red[k]; smu = s * (1.f / 160.f); }
        __syncthreads();
        float d = z - smu;
        red[c] = d * d;
        __syncthreads();
        if (c == 0) { float s = 0.f; for (int k = 0; k < HID; k++) s += red[k]; srstd = rsqrtf(s * (1.f / 160.f) + 1e-5f); }
        __syncthreads();
        float zn = d * srstd * lns[c] + lnb[c];
        zn = zn > 0.f ? zn : 0.f;
        sz[c] = zn;
        __syncthreads();
        if (c < NC) {
            float r = b2[c];
            for (int k = 0; k < HID; k++) r += sz[k] * W2[k * NC + c];
            rec[g * NC + c] = r;
        }
        __syncthreads();
    }
}

// ---------------- launcher ----------------
extern "C" void kernel_launch(void* const* d_in, const int* in_sizes, int n_in,
                              void* d_out, int out_size)
{
    const float* x     = (const float*)d_in[0];
    const void*  ei    = d_in[1];
    const void*  batch = d_in[2];
    const float* W1    = (const float*)d_in[3];
    const float* as1   = (const float*)d_in[4];
    const float* ad1   = (const float*)d_in[5];
    const float* b1    = (const float*)d_in[6];
    const float* l1s   = (const float*)d_in[7];
    const float* l1b   = (const float*)d_in[8];
    const float* W2    = (const float*)d_in[9];
    const float* as2   = (const float*)d_in[10];
    const float* ad2   = (const float*)d_in[11];
    const float* b2    = (const float*)d_in[12];
    const float* l2s   = (const float*)d_in[13];
    const float* l2b   = (const float*)d_in[14];
    const float* Wm    = (const float*)d_in[15];
    const float* bm    = (const float*)d_in[16];
    const float* Wm1   = (const float*)d_in[17];
    const float* bm1   = (const float*)d_in[18];
    const float* l3s   = (const float*)d_in[19];
    const float* l3b   = (const float*)d_in[20];
    const float* Wm2   = (const float*)d_in[21];
    const float* bm2   = (const float*)d_in[22];

    int N   = in_sizes[2];
    int E   = in_sizes[1] / 2;
    int FIN = in_sizes[0] / N;
    int Et  = E + N;

    float* feat;   cudaGetSymbolAddress((void**)&feat,   g_feat);
    float* hidden; cudaGetSymbolAddress((void**)&hidden, g_hidden);

    float* xo     = (float*)d_out;
    float* rec    = xo + (long long)N * HID;
    float* alpha1 = rec + NG * NC;
    float* alpha2 = alpha1 + (long long)Et * H;

    int gE  = (Et + 255) / 256;          // per-edge kernels
    int gN  = (N + 255) / 256;           // per-node scalar kernels
    int gW  = (N * 32 + 255) / 256;      // warp-per-node kernels
    int gM  = (N + 63) / 64;             // GEMM blocks
    int gSM = (N * H + 255) / 256;

    detect_kernel<<<1, 32>>>(ei);
    // CSR build (shared by both layers)
    zero_csr_kernel<<<gN, 256>>>(N);
    count_kernel<<<gE, 256>>>(ei, E, N);
    scan_kernel<<<1, 1024>>>(N);
    copy_cursor_kernel<<<gN, 256>>>(N);
    fill_kernel<<<gE, 256>>>(ei, E, N);

    // ---- layer 1 ----
    gemm_kernel<<<gM, 256>>>(x, W1, feat, N, FIN, nullptr, 0);
    attcoef_kernel<<<gW, 256>>>(feat, as1, ad1, N);
    zero_sm_kernel<<<gSM, 256>>>(N * H);
    edge_max_kernel<<<gE, 256>>>(ei, E, N);
    edge_exp_kernel<<<gE, 256>>>(ei, alpha1, E, N);
    aggregate_kernel<<<gW, 256>>>(ei, E, alpha1, b1, l1s, l1b, N);

    // ---- layer 2 ----
    gemm_kernel<<<gM, 256>>>(hidden, W2, feat, N, HID, nullptr, 0);
    attcoef_kernel<<<gW, 256>>>(feat, as2, ad2, N);
    zero_sm_kernel<<<gSM, 256>>>(N * H);
    edge_max_kernel<<<gE, 256>>>(ei, E, N);
    edge_exp_kernel<<<gE, 256>>>(ei, alpha2, E, N);
    aggregate_kernel<<<gW, 256>>>(ei, E, alpha2, b2, l2s, l2b, N);

    // ---- xo = leaky(h2 @ Wm + bm) ----
    gemm_kernel<<<gM, 256>>>(hidden, Wm, xo, N, HID, bm, 1);

    // ---- pool + MLP head ----
    zero_pool_kernel<<<(NG * HID + 255) / 256, 256>>>();
    pool_kernel<<<(N + 127) / 128, 160>>>(xo, batch, N);
    mlp_kernel<<<1, 160>>>(Wm1, bm1, l3s, l3b, Wm2, bm2, rec);
}

// round 5
// speedup vs baseline: 1.1009x; 1.1009x over previous
#include <cuda_runtime.h>

#define H 5
#define HID 160
#define NG 8
#define NC 20
#define MAXN 50000
#define MAXE 800000
#define MAXET (MAXN + MAXE)

// ---------------- device scratch (static; no runtime allocation) ----------------
__device__ float    g_feat[MAXN * HID];     // h = x @ W (pre-aggregation features)
__device__ float    g_hidden[MAXN * HID];   // layer outputs
__device__ float    g_als[MAXN * H];
__device__ float    g_ald[MAXN * H];
__device__ unsigned g_maxu[MAXN * H];
__device__ float    g_sum[MAXN * H];
__device__ int      g_rowptr[MAXN + 1];
__device__ int      g_cursor[MAXN];
__device__ int      g_cnt[MAXN];
__device__ int      g_eids[MAXET];
__device__ float    g_pool[NG * HID];
__device__ int      g_gcnt[NG];
__device__ int      g_idx64;

// ---------------- helpers ----------------
__device__ __forceinline__ long long ldidx(const void* p, long long i) {
    return g_idx64 ? ((const long long*)p)[i] : (long long)((const int*)p)[i];
}
__device__ __forceinline__ unsigned fkey(float f) {
    unsigned u = __float_as_uint(f);
    return (u & 0x80000000u) ? ~u : (u | 0x80000000u);
}
__device__ __forceinline__ float fdec(unsigned k) {
    return (k & 0x80000000u) ? __uint_as_float(k & 0x7fffffffu)
                             : __uint_as_float(~k);
}
__device__ __forceinline__ unsigned f2tf32(float x) {
    unsigned r;
    asm("cvt.rna.tf32.f32 %0, %1;" : "=r"(r) : "f"(x));
    return r;
}
__device__ __forceinline__ void mma8(float* c, const unsigned* a, unsigned b0, unsigned b1) {
    asm volatile("mma.sync.aligned.m16n8k8.row.col.f32.tf32.tf32.f32 "
                 "{%0,%1,%2,%3}, {%4,%5,%6,%7}, {%8,%9}, {%0,%1,%2,%3};\n"
                 : "+f"(c[0]), "+f"(c[1]), "+f"(c[2]), "+f"(c[3])
                 : "r"(a[0]), "r"(a[1]), "r"(a[2]), "r"(a[3]), "r"(b0), "r"(b1));
}

// ---------------- index dtype detection ----------------
__global__ void detect_kernel(const void* ei) {
    if (blockIdx.x == 0 && threadIdx.x == 0) {
        const int* p = (const int*)ei;
        int is64 = 1;
        for (int i = 0; i < 512; ++i)
            if (p[2 * i + 1] != 0) { is64 = 0; break; }
        g_idx64 = is64;
    }
}

// ---------------- CSR build (dst-sorted edge list) ----------------
__global__ void zero_csr_kernel(int n) {
    int i = blockIdx.x * blockDim.x + threadIdx.x;
    if (i < n) g_cnt[i] = 0;
}

__global__ void count_kernel(const void* ei, int E, int N) {
    int e = blockIdx.x * blockDim.x + threadIdx.x;
    if (e >= E + N) return;
    int d = (e < E) ? (int)ldidx(ei, (long long)E + e) : (e - E);
    atomicAdd(&g_cnt[d], 1);
}

// Single-block scan: thread-sequential chunks + warp-shuffle block scan.
// Also writes g_cursor (fuses the old copy_cursor kernel).
__global__ void scan_kernel(int n) {
    const int T = 1024;
    int tid = threadIdx.x;
    int L = (n + T - 1) / T;
    int s0 = tid * L;
    int s1 = s0 + L; if (s1 > n) s1 = n;
    int local = 0;
    for (int i = s0; i < s1; ++i) local += g_cnt[i];

    int lane = tid & 31, wid = tid >> 5;
    int v = local;
#pragma unroll
    for (int off = 1; off < 32; off <<= 1) {
        int u = __shfl_up_sync(0xffffffffu, v, off);
        if (lane >= off) v += u;
    }
    __shared__ int wsum[32];
    if (lane == 31) wsum[wid] = v;
    __syncthreads();
    if (wid == 0) {
        int wv = wsum[lane];
#pragma unroll
        for (int off = 1; off < 32; off <<= 1) {
            int u = __shfl_up_sync(0xffffffffu, wv, off);
            if (lane >= off) wv += u;
        }
        wsum[lane] = wv;
    }
    __syncthreads();
    int excl = v - local + (wid ? wsum[wid - 1] : 0);

    int run = excl;
    for (int i = s0; i < s1; ++i) {
        int c = g_cnt[i];
        g_rowptr[i] = run;
        g_cursor[i] = run;
        run += c;
    }
    if (tid == T - 1) g_rowptr[n] = run;
}

__global__ void fill_kernel(const void* ei, int E, int N) {
    int e = blockIdx.x * blockDim.x + threadIdx.x;
    if (e >= E + N) return;
    int d = (e < E) ? (int)ldidx(ei, (long long)E + e) : (e - E);
    int pos = atomicAdd(&g_cursor[d], 1);
    g_eids[pos] = e;
}

// ---------------- tensor-core GEMM: C[M,160] = A[M,K] @ W[K,160] ----------------
// mma.sync.m16n8k8 tf32 with 3xTF32 split (fp32-class accuracy).
// BM=128 (8 warps x 16 rows), BN=160 (20 n-tiles), BK=32.
// mode act=1: +bias, leaky(0.01). mode act=0: also emits al_s/al_d attention
// coefficients from the in-register output row (fused attcoef).
__global__ __launch_bounds__(256) void gemm_mma_kernel(
    const float* __restrict__ A, const float* __restrict__ W, float* __restrict__ C,
    int M, int K,
    const float* __restrict__ bias, int act,
    const float* __restrict__ asrc, const float* __restrict__ adst,
    float* __restrict__ als, float* __restrict__ ald)
{
    __shared__ float sA[128][36];
    __shared__ float sB[32][168];
    int tid = threadIdx.x;
    int w = tid >> 5, lane = tid & 31;
    int g = lane >> 2, t = lane & 3;
    int r0 = blockIdx.x * 128;

    float acc[20][4];
#pragma unroll
    for (int i = 0; i < 20; i++)
#pragma unroll
        for (int j = 0; j < 4; j++) acc[i][j] = 0.f;

    int kt = (K + 31) / 32;
    for (int kb = 0; kb < kt; ++kb) {
        int k0 = kb * 32;
        bool full = (k0 + 32 <= K);
        // --- load A tile (128 x 32) ---
#pragma unroll
        for (int p = 0; p < 4; ++p) {
            int row = p * 32 + (tid >> 3);
            int c = (tid & 7) * 4;
            int gr = r0 + row;
            float4 v = make_float4(0.f, 0.f, 0.f, 0.f);
            if (gr < M) {
                if (full) {
                    v = *(const float4*)(A + (long long)gr * K + k0 + c);
                } else {
                    float tmp[4];
#pragma unroll
                    for (int j = 0; j < 4; ++j) {
                        int gk = k0 + c + j;
                        tmp[j] = (gk < K) ? A[(long long)gr * K + gk] : 0.f;
                    }
                    v = make_float4(tmp[0], tmp[1], tmp[2], tmp[3]);
                }
            }
            *(float4*)&sA[row][c] = v;
        }
        // --- load B tile (32 x 160) ---
#pragma unroll
        for (int p = 0; p < 20; ++p) {
            int idx = tid + p * 256;
            int k = idx / 160, nn = idx % 160;
            int gk = k0 + k;
            sB[k][nn] = (gk < K) ? W[gk * 160 + nn] : 0.f;
        }
        __syncthreads();
#pragma unroll
        for (int kk = 0; kk < 32; kk += 8) {
            float af[4];
            af[0] = sA[16 * w + g][kk + t];
            af[1] = sA[16 * w + g + 8][kk + t];
            af[2] = sA[16 * w + g][kk + t + 4];
            af[3] = sA[16 * w + g + 8][kk + t + 4];
            unsigned abig[4], asml[4];
#pragma unroll
            for (int j = 0; j < 4; ++j) {
                abig[j] = f2tf32(af[j]);
                asml[j] = f2tf32(af[j] - __uint_as_float(abig[j]));
            }
#pragma unroll
            for (int tile = 0; tile < 20; ++tile) {
                float b0 = sB[kk + t][8 * tile + g];
                float b1 = sB[kk + t + 4][8 * tile + g];
                unsigned bb0 = f2tf32(b0), bb1 = f2tf32(b1);
                unsigned bs0 = f2tf32(b0 - __uint_as_float(bb0));
                unsigned bs1 = f2tf32(b1 - __uint_as_float(bb1));
                mma8(acc[tile], abig, bb0, bb1);
                mma8(acc[tile], abig, bs0, bs1);
                mma8(acc[tile], asml, bb0, bb1);
            }
        }
        __syncthreads();
    }

    int row0 = r0 + 16 * w + g;
    int row1 = row0 + 8;
    if (act) {
#pragma unroll
        for (int tile = 0; tile < 20; ++tile) {
            int c0 = 8 * tile + 2 * t;
            float bv0 = bias[c0], bv1 = bias[c0 + 1];
            if (row0 < M) {
                float v0 = acc[tile][0] + bv0; v0 = v0 > 0.f ? v0 : 0.01f * v0;
                float v1 = acc[tile][1] + bv1; v1 = v1 > 0.f ? v1 : 0.01f * v1;
                *(float2*)(C + (long long)row0 * 160 + c0) = make_float2(v0, v1);
            }
            if (row1 < M) {
                float v2 = acc[tile][2] + bv0; v2 = v2 > 0.f ? v2 : 0.01f * v2;
                float v3 = acc[tile][3] + bv1; v3 = v3 > 0.f ? v3 : 0.01f * v3;
                *(float2*)(C + (long long)row1 * 160 + c0) = make_float2(v2, v3);
            }
        }
    } else {
        float ps0[5], pd0[5], ps1[5], pd1[5];
#pragma unroll
        for (int h = 0; h < 5; ++h) { ps0[h] = pd0[h] = ps1[h] = pd1[h] = 0.f; }
#pragma unroll
        for (int tile = 0; tile < 20; ++tile) {
            int c0 = 8 * tile + 2 * t;
            if (row0 < M)
                *(float2*)(C + (long long)row0 * 160 + c0) = make_float2(acc[tile][0], acc[tile][1]);
            if (row1 < M)
                *(float2*)(C + (long long)row1 * 160 + c0) = make_float2(acc[tile][2], acc[tile][3]);
            int h = tile >> 2;   // head = col/32, constant within a tile
            float w0s = asrc[c0], w1s = asrc[c0 + 1];
            float w0d = adst[c0], w1d = adst[c0 + 1];
            ps0[h] += acc[tile][0] * w0s + acc[tile][1] * w1s;
            pd0[h] += acc[tile][0] * w0d + acc[tile][1] * w1d;
            ps1[h] += acc[tile][2] * w0s + acc[tile][3] * w1s;
            pd1[h] += acc[tile][2] * w0d + acc[tile][3] * w1d;
        }
#pragma unroll
        for (int h = 0; h < 5; ++h) {
            ps0[h] += __shfl_xor_sync(0xffffffffu, ps0[h], 1);
            ps0[h] += __shfl_xor_sync(0xffffffffu, ps0[h], 2);
            pd0[h] += __shfl_xor_sync(0xffffffffu, pd0[h], 1);
            pd0[h] += __shfl_xor_sync(0xffffffffu, pd0[h], 2);
            ps1[h] += __shfl_xor_sync(0xffffffffu, ps1[h], 1);
            ps1[h] += __shfl_xor_sync(0xffffffffu, ps1[h], 2);
            pd1[h] += __shfl_xor_sync(0xffffffffu, pd1[h], 1);
            pd1[h] += __shfl_xor_sync(0xffffffffu, pd1[h], 2);
        }
        if (t == 0) {
            if (row0 < M) {
#pragma unroll
                for (int h = 0; h < 5; ++h) {
                    als[row0 * H + h] = ps0[h];
                    ald[row0 * H + h] = pd0[h];
                }
            }
            if (row1 < M) {
#pragma unroll
                for (int h = 0; h < 5; ++h) {
                    als[row1 * H + h] = ps1[h];
                    ald[row1 * H + h] = pd1[h];
                }
            }
        }
    }
}

__global__ void zero_sm_kernel(int n) {
    int i = blockIdx.x * blockDim.x + threadIdx.x;
    if (i < n) { g_maxu[i] = 0u; g_sum[i] = 0.f; }
}

// ---------------- edge softmax pass 1: segment max (caches logits in alpha) -----
__global__ void edge_max_kernel(const void* ei, float* __restrict__ alpha, int E, int N) {
    int e = blockIdx.x * blockDim.x + threadIdx.x;
    if (e >= E + N) return;
    int s, d;
    if (e < E) { s = (int)ldidx(ei, e); d = (int)ldidx(ei, (long long)E + e); }
    else       { s = d = e - E; }
#pragma unroll
    for (int h = 0; h < H; h++) {
        float l = g_als[s * H + h] + g_ald[d * H + h];
        l = l > 0.f ? l : 0.2f * l;
        alpha[(long long)e * H + h] = l;
        atomicMax(&g_maxu[d * H + h], fkey(l));
    }
}

// ---------------- edge softmax pass 2: exp + segment sum ----------------
__global__ void edge_exp_kernel(const void* ei, float* __restrict__ alpha, int E, int N) {
    int e = blockIdx.x * blockDim.x + threadIdx.x;
    if (e >= E + N) return;
    int d = (e < E) ? (int)ldidx(ei, (long long)E + e) : (e - E);
#pragma unroll
    for (int h = 0; h < H; h++) {
        float l  = alpha[(long long)e * H + h];
        float m  = fdec(g_maxu[d * H + h]);
        float ex = expf(l - m);
        alpha[(long long)e * H + h] = ex;
        atomicAdd(&g_sum[d * H + h], ex);
    }
}

// ---------------- aggregation + alpha normalize + bias + leaky + LayerNorm -------
__global__ __launch_bounds__(256) void aggregate_kernel(
    const void* ei, int E,
    float* __restrict__ alpha,            // in: exp values; out: normalized
    const float* __restrict__ bias,
    const float* __restrict__ lns, const float* __restrict__ lnb,
    int N)
{
    int warp = (blockIdx.x * blockDim.x + threadIdx.x) >> 5;
    int lane = threadIdx.x & 31;
    if (warp >= N) return;
    int n = warp;

    float sinv = 0.f;
    if (lane < H) sinv = 1.f / (g_sum[n * H + lane] + 1e-16f);

    float acc0 = 0.f, acc1 = 0.f, acc2 = 0.f, acc3 = 0.f, acc4 = 0.f;
    int p0 = g_rowptr[n], p1 = g_rowptr[n + 1];
    for (int p = p0; p < p1; ++p) {
        int e = g_eids[p];
        int s = (e < E) ? (int)ldidx(ei, e) : (e - E);
        float an = 0.f;
        if (lane < H) {
            an = alpha[(long long)e * H + lane] * sinv;
            alpha[(long long)e * H + lane] = an;
        }
        float a0 = __shfl_sync(0xffffffffu, an, 0);
        float a1 = __shfl_sync(0xffffffffu, an, 1);
        float a2 = __shfl_sync(0xffffffffu, an, 2);
        float a3 = __shfl_sync(0xffffffffu, an, 3);
        float a4 = __shfl_sync(0xffffffffu, an, 4);
        const float* f = g_feat + (long long)s * HID;
        acc0 += f[lane]       * a0;
        acc1 += f[32 + lane]  * a1;
        acc2 += f[64 + lane]  * a2;
        acc3 += f[96 + lane]  * a3;
        acc4 += f[128 + lane] * a4;
    }
    float v0 = acc0 + bias[lane];        v0 = v0 > 0.f ? v0 : 0.01f * v0;
    float v1 = acc1 + bias[32 + lane];   v1 = v1 > 0.f ? v1 : 0.01f * v1;
    float v2 = acc2 + bias[64 + lane];   v2 = v2 > 0.f ? v2 : 0.01f * v2;
    float v3 = acc3 + bias[96 + lane];   v3 = v3 > 0.f ? v3 : 0.01f * v3;
    float v4 = acc4 + bias[128 + lane];  v4 = v4 > 0.f ? v4 : 0.01f * v4;
    float sum = v0 + v1 + v2 + v3 + v4;
#pragma unroll
    for (int off = 16; off; off >>= 1) sum += __shfl_xor_sync(0xffffffffu, sum, off);
    float mu = sum * (1.f / 160.f);
    float d0 = v0 - mu, d1 = v1 - mu, d2 = v2 - mu, d3 = v3 - mu, d4 = v4 - mu;
    float sq = d0 * d0 + d1 * d1 + d2 * d2 + d3 * d3 + d4 * d4;
#pragma unroll
    for (int off = 16; off; off >>= 1) sq += __shfl_xor_sync(0xffffffffu, sq, off);
    float rstd = rsqrtf(sq * (1.f / 160.f) + 1e-5f);
    float* o = g_hidden + (long long)n * HID;
    o[lane]       = d0 * rstd * lns[lane]       + lnb[lane];
    o[32 + lane]  = d1 * rstd * lns[32 + lane]  + lnb[32 + lane];
    o[64 + lane]  = d2 * rstd * lns[64 + lane]  + lnb[64 + lane];
    o[96 + lane]  = d3 * rstd * lns[96 + lane]  + lnb[96 + lane];
    o[128 + lane] = d4 * rstd * lns[128 + lane] + lnb[128 + lane];
}

// ---------------- pooling ----------------
__global__ void zero_pool_kernel() {
    int i = blockIdx.x * blockDim.x + threadIdx.x;
    if (i < NG * HID) g_pool[i] = 0.f;
    if (i < NG) g_gcnt[i] = 0;
}

__global__ void pool_kernel(const float* __restrict__ xo, const void* batchp, int N) {
    int c  = threadIdx.x;                 // 160 threads
    int n0 = blockIdx.x * 128;
    int n1 = n0 + 128; if (n1 > N) n1 = N;
    float acc = 0.f; int cur = -1; int cnt = 0;
    for (int n = n0; n < n1; ++n) {
        int g = (int)ldidx(batchp, n);
        if (g != cur) {
            if (cur >= 0) {
                atomicAdd(&g_pool[cur * HID + c], acc);
                if (c == 0) atomicAdd(&g_gcnt[cur], cnt);
            }
            acc = 0.f; cnt = 0; cur = g;
        }
        acc += xo[(long long)n * HID + c];
        cnt++;
    }
    if (cur >= 0) {
        atomicAdd(&g_pool[cur * HID + c], acc);
        if (c == 0) atomicAdd(&g_gcnt[cur], cnt);
    }
}

// ---------------- tiny MLP head ----------------
__global__ void mlp_kernel(const float* __restrict__ W1, const float* __restrict__ b1,
                           const float* __restrict__ lns, const float* __restrict__ lnb,
                           const float* __restrict__ W2, const float* __restrict__ b2,
                           float* __restrict__ rec)
{
    __shared__ float sp[NG][HID];
    __shared__ float sz[HID];
    __shared__ float red[HID];
    __shared__ float smu, srstd;
    int c = threadIdx.x;                  // 160 threads
    for (int g = 0; g < NG; g++) {
        float cf = (float)g_gcnt[g];
        if (cf < 1.f) cf = 1.f;
        sp[g][c] = g_pool[g * HID + c] / cf;
    }
    __syncthreads();
    for (int g = 0; g < NG; g++) {
        float z = b1[c];
        for (int k = 0; k < HID; k++) z += sp[g][k] * W1[k * HID + c];
        red[c] = z;
        __syncthreads();
        if (c == 0) { float s = 0.f; for (int k = 0; k < HID; k++) s += red[k]; smu = s * (1.f / 160.f); }
        __syncthreads();
        float d = z - smu;
        red[c] = d * d;
        __syncthreads();
        if (c == 0) { float s = 0.f; for (int k = 0; k < HID; k++) s += red[k]; srstd = rsqrtf(s * (1.f / 160.f) + 1e-5f); }
        __syncthreads();
        float zn = d * srstd * lns[c] + lnb[c];
        zn = zn > 0.f ? zn : 0.f;
        sz[c] = zn;
        __syncthreads();
        if (c < NC) {
            float r = b2[c];
            for (int k = 0; k < HID; k++) r += sz[k] * W2[k * NC + c];
            rec[g * NC + c] = r;
        }
        __syncthreads();
    }
}

// ---------------- launcher ----------------
extern "C" void kernel_launch(void* const* d_in, const int* in_sizes, int n_in,
                              void* d_out, int out_size)
{
    const float* x     = (const float*)d_in[0];
    const void*  ei    = d_in[1];
    const void*  batch = d_in[2];
    const float* W1    = (const float*)d_in[3];
    const float* as1   = (const float*)d_in[4];
    const float* ad1   = (const float*)d_in[5];
    const float* b1    = (const float*)d_in[6];
    const float* l1s   = (const float*)d_in[7];
    const float* l1b   = (const float*)d_in[8];
    const float* W2    = (const float*)d_in[9];
    const float* as2   = (const float*)d_in[10];
    const float* ad2   = (const float*)d_in[11];
    const float* b2    = (const float*)d_in[12];
    const float* l2s   = (const float*)d_in[13];
    const float* l2b   = (const float*)d_in[14];
    const float* Wm    = (const float*)d_in[15];
    const float* bm    = (const float*)d_in[16];
    const float* Wm1   = (const float*)d_in[17];
    const float* bm1   = (const float*)d_in[18];
    const float* l3s   = (const float*)d_in[19];
    const float* l3b   = (const float*)d_in[20];
    const float* Wm2   = (const float*)d_in[21];
    const float* bm2   = (const float*)d_in[22];

    int N   = in_sizes[2];
    int E   = in_sizes[1] / 2;
    int FIN = in_sizes[0] / N;
    int Et  = E + N;

    float* feat;   cudaGetSymbolAddress((void**)&feat,   g_feat);
    float* hidden; cudaGetSymbolAddress((void**)&hidden, g_hidden);
    float* alsp;   cudaGetSymbolAddress((void**)&alsp,   g_als);
    float* aldp;   cudaGetSymbolAddress((void**)&aldp,   g_ald);

    float* xo     = (float*)d_out;
    float* rec    = xo + (long long)N * HID;
    float* alpha1 = rec + NG * NC;
    float* alpha2 = alpha1 + (long long)Et * H;

    int gE  = (Et + 255) / 256;          // per-edge kernels
    int gN  = (N + 255) / 256;           // per-node scalar kernels
    int gW  = (N * 32 + 255) / 256;      // warp-per-node kernels
    int gM  = (N + 127) / 128;           // GEMM blocks (BM=128)
    int gSM = (N * H + 255) / 256;

    detect_kernel<<<1, 32>>>(ei);
    // CSR build (shared by both layers)
    zero_csr_kernel<<<gN, 256>>>(N);
    count_kernel<<<gE, 256>>>(ei, E, N);
    scan_kernel<<<1, 1024>>>(N);         // also writes g_cursor
    fill_kernel<<<gE, 256>>>(ei, E, N);

    // ---- layer 1 ----
    gemm_mma_kernel<<<gM, 256>>>(x, W1, feat, N, FIN, nullptr, 0, as1, ad1, alsp, aldp);
    zero_sm_kernel<<<gSM, 256>>>(N * H);
    edge_max_kernel<<<gE, 256>>>(ei, alpha1, E, N);
    edge_exp_kernel<<<gE, 256>>>(ei, alpha1, E, N);
    aggregate_kernel<<<gW, 256>>>(ei, E, alpha1, b1, l1s, l1b, N);

    // ---- layer 2 ----
    gemm_mma_kernel<<<gM, 256>>>(hidden, W2, feat, N, HID, nullptr, 0, as2, ad2, alsp, aldp);
    zero_sm_kernel<<<gSM, 256>>>(N * H);
    edge_max_kernel<<<gE, 256>>>(ei, alpha2, E, N);
    edge_exp_kernel<<<gE, 256>>>(ei, alpha2, E, N);
    aggregate_kernel<<<gW, 256>>>(ei, E, alpha2, b2, l2s, l2b, N);

    // ---- xo = leaky(h2 @ Wm + bm) ----
    gemm_mma_kernel<<<gM, 256>>>(hidden, Wm, xo, N, HID, bm, 1, nullptr, nullptr, nullptr, nullptr);

    // ---- pool + MLP head ----
    zero_pool_kernel<<<(NG * HID + 255) / 256, 256>>>();
    pool_kernel<<<(N + 127) / 128, 160>>>(xo, batch, N);
    mlp_kernel<<<1, 160>>>(Wm1, bm1, l3s, l3b, Wm2, bm2, rec);
}